// round 3
// baseline (speedup 1.0000x reference)
#include <cuda_runtime.h>

#define PI_F 3.14159265358979323846f

// ---------------- constant tables computed on-device from the small inputs ----
struct Params {
    float4 pair[136];   // (i<=j) upper-tri order: {a,a,b,b}, off-diag pre-doubled
    float  K[9];        // e = sum K[3r+s] * (1,C1,S1)_r * (1,C2,S2)_s
    float  W0, W1, b0, b1;
};
__device__ Params g_params;

// compile-time 16th-root twiddle table: W16[k] = (cos, sin)(2*pi*k/16)
__constant__ float2 W16[16] = {
    { 1.0000000000f,  0.0000000000f}, { 0.9238795325f,  0.3826834324f},
    { 0.7071067812f,  0.7071067812f}, { 0.3826834324f,  0.9238795325f},
    { 0.0000000000f,  1.0000000000f}, {-0.3826834324f,  0.9238795325f},
    {-0.7071067812f,  0.7071067812f}, {-0.9238795325f,  0.3826834324f},
    {-1.0000000000f,  0.0000000000f}, {-0.9238795325f, -0.3826834324f},
    {-0.7071067812f, -0.7071067812f}, {-0.3826834324f, -0.9238795325f},
    { 0.0000000000f, -1.0000000000f}, { 0.3826834324f, -0.9238795325f},
    { 0.7071067812f, -0.7071067812f}, { 0.9238795325f, -0.3826834324f}};

__device__ __forceinline__ float2 cmulf(float2 a, float2 b) {
    return make_float2(a.x * b.x - a.y * b.y, a.x * b.y + a.y * b.x);
}

// ---------------- setup: build U1 (16x16), U2 (4x4), fold into A/B/K ---------
__global__ void setup_kernel(const float* __restrict__ f1, const float* __restrict__ p1,
                             const float* __restrict__ f2, const float* __restrict__ p2,
                             const float* __restrict__ W, const float* __restrict__ bb) {
    __shared__ float2 U[256];
    __shared__ float2 V[256];
    __shared__ float2 U2s[16];
    __shared__ float2 V2s[16];

    const int t = threadIdx.x;
    const int r = t >> 4, c = t & 15;
    const float p1_0 = p1[0], p1_1 = p1[1];
    float sn_p11, cs_p11; sincosf(0.5f * p1_1, &sn_p11, &cs_p11);

    // ---- U1: init = (fused RZ diag) * QFT ----
    {
        float ph = 0.0f;
        ph += (((r >> 3) & 1) ? 0.5f : -0.5f) * f1[0];
        ph += (((r >> 2) & 1) ? 0.5f : -0.5f) * f1[1];
        ph += (((r >> 1) & 1) ? 0.5f : -0.5f) * f1[2];
        ph += (((r     ) & 1) ? 0.5f : -0.5f) * f1[3];
        float sp, cp; sincosf(ph, &sp, &cp);
        float2 w = W16[(r * c) & 15];
        U[t] = make_float2(0.25f * (w.x * cp - w.y * sp),
                           0.25f * (w.y * cp + w.x * sp));
    }
    __syncthreads();
    // Qdag @ U  (the only dense matmul) — twiddle conj from the constant table
    {
        float2 acc = make_float2(0.f, 0.f);
        #pragma unroll
        for (int k = 0; k < 16; ++k) {
            float2 w = W16[(r * k) & 15];      // conj(w) = (w.x, -w.y)
            float2 u = U[k * 16 + c];
            acc.x += w.x * u.x + w.y * u.y;
            acc.y += w.x * u.y - w.y * u.x;
        }
        V[t] = make_float2(0.25f * acc.x, 0.25f * acc.y);
    }
    __syncthreads();
    U[t] = V[t];
    __syncthreads();

    // g1: CRZ(p1_0) ctrl bit3, tgt bit2 (diag in-place)
    if ((r >> 3) & 1) {
        float ang = (((r >> 2) & 1) ? 0.5f : -0.5f) * p1_0;
        float sn, cs; sincosf(ang, &sn, &cs);
        U[t] = cmulf(U[t], make_float2(cs, sn));
    }
    __syncthreads();
    // g2: X mask 8
    V[t] = U[((r ^ 8) << 4) | c]; __syncthreads(); U[t] = V[t]; __syncthreads();
    // g3: CRX(p1_1) ctrl bit3, tgt mask 4
    {
        float2 u = U[t];
        if ((r >> 3) & 1) {
            float2 v = U[((r ^ 4) << 4) | c];
            u = make_float2(cs_p11 * u.x + sn_p11 * v.y, cs_p11 * u.y - sn_p11 * v.x);
        }
        V[t] = u;
    }
    __syncthreads(); U[t] = V[t]; __syncthreads();
    // g4: X mask 8
    V[t] = U[((r ^ 8) << 4) | c]; __syncthreads(); U[t] = V[t]; __syncthreads();
    // g5: CRZ(p1_0) ctrl bit1, tgt bit0
    if ((r >> 1) & 1) {
        float ang = ((r & 1) ? 0.5f : -0.5f) * p1_0;
        float sn, cs; sincosf(ang, &sn, &cs);
        U[t] = cmulf(U[t], make_float2(cs, sn));
    }
    __syncthreads();
    // g6: X mask 2
    V[t] = U[((r ^ 2) << 4) | c]; __syncthreads(); U[t] = V[t]; __syncthreads();
    // g7: CRX(p1_1) ctrl bit1, tgt mask 1
    {
        float2 u = U[t];
        if ((r >> 1) & 1) {
            float2 v = U[((r ^ 1) << 4) | c];
            u = make_float2(cs_p11 * u.x + sn_p11 * v.y, cs_p11 * u.y - sn_p11 * v.x);
        }
        V[t] = u;
    }
    __syncthreads(); U[t] = V[t]; __syncthreads();
    // g8: X mask 2
    V[t] = U[((r ^ 2) << 4) | c]; __syncthreads(); U[t] = V[t]; __syncthreads();

    // ---- pair table: A = Re(U1^H Z1 U1), B = Re(U1^H Z3 U1) ----
    if (r <= c) {
        const int i = r, j = c;
        float av = 0.f, bv = 0.f;
        #pragma unroll
        for (int m = 0; m < 16; ++m) {
            float2 ui = U[m * 16 + i], uj = U[m * 16 + j];
            float re = ui.x * uj.x + ui.y * uj.y;     // Re(conj(ui)*uj)
            float z1 = 1.f - 2.f * (float)((m >> 2) & 1);
            float z3 = 1.f - 2.f * (float)(m & 1);
            av += z1 * re;
            bv += z3 * re;
        }
        float w = (i < j) ? 2.f : 1.f;
        int idx = i * 16 - (i * (i - 1)) / 2 + (j - i);
        g_params.pair[idx] = make_float4(w * av, w * av, w * bv, w * bv);
    }

    // ---- U2 (4x4) ----
    if (t < 16) {
        int r2 = t >> 2, c2 = t & 3;
        float ph = ((((r2 >> 1) & 1) ? 0.5f : -0.5f) * f2[0])
                 + ((( r2       & 1) ? 0.5f : -0.5f) * f2[1]);
        float sp, cp; sincosf(ph, &sp, &cp);
        float2 w = W16[((r2 * c2) & 3) * 4];
        U2s[t] = make_float2(0.5f * (w.x * cp - w.y * sp),
                             0.5f * (w.y * cp + w.x * sp));
    }
    __syncthreads();
    if (t < 16) {  // Q2dag @ U2
        int r2 = t >> 2, c2 = t & 3;
        float2 acc = make_float2(0.f, 0.f);
        #pragma unroll
        for (int k = 0; k < 4; ++k) {
            float2 w = W16[((r2 * k) & 3) * 4];   // use conj(w)
            float2 u = U2s[k * 4 + c2];
            acc.x += w.x * u.x + w.y * u.y;
            acc.y += w.x * u.y - w.y * u.x;
        }
        V2s[t] = make_float2(0.5f * acc.x, 0.5f * acc.y);
    }
    __syncthreads();
    if (t < 16) {  // CRZ(p2[0]) ctrl bit1, tgt bit0
        int r2 = t >> 2;
        float2 u = V2s[t];
        if ((r2 >> 1) & 1) {
            float ang = ((r2 & 1) ? 0.5f : -0.5f) * p2[0];
            float sn, cs; sincosf(ang, &sn, &cs);
            u = cmulf(u, make_float2(cs, sn));
        }
        U2s[t] = u;
    }
    __syncthreads();
    if (t < 16) {  // X mask 2
        int r2 = t >> 2, c2 = t & 3;
        V2s[t] = U2s[((r2 ^ 2) << 2) | c2];
    }
    __syncthreads();
    if (t < 16) {  // CRX(p2[1]) ctrl bit1, tgt mask 1
        int r2 = t >> 2, c2 = t & 3;
        float2 u = V2s[t];
        if ((r2 >> 1) & 1) {
            float sn, cs; sincosf(0.5f * p2[1], &sn, &cs);
            float2 v = V2s[((r2 ^ 1) << 2) | c2];
            u = make_float2(cs * u.x + sn * v.y, cs * u.y - sn * v.x);
        }
        U2s[t] = u;
    }
    __syncthreads();
    if (t < 16) {  // X mask 2 (final U2 ends in V2s)
        int r2 = t >> 2, c2 = t & 3;
        V2s[t] = U2s[((r2 ^ 2) << 2) | c2];
    }
    __syncthreads();

    // ---- fold layer-2 into K ----
    if (t == 0) {
        float C[4][4];
        #pragma unroll
        for (int i = 0; i < 4; ++i)
            #pragma unroll
            for (int j = 0; j < 4; ++j) {
                float acc = 0.f;
                #pragma unroll
                for (int m = 0; m < 4; ++m) {
                    float2 ui = V2s[m * 4 + i], uj = V2s[m * 4 + j];
                    float z = 1.f - 2.f * (float)(m & 1);
                    acc += z * (ui.x * uj.x + ui.y * uj.y);
                }
                C[i][j] = acc;
            }
        float T[3][3];
        T[0][0] = C[0][0];            T[0][1] = 2.f * C[0][1];                   T[0][2] = C[1][1];
        T[1][0] = 2.f * C[0][2];      T[1][1] = 2.f * C[0][3] + 2.f * C[1][2];   T[1][2] = 2.f * C[1][3];
        T[2][0] = C[2][2];            T[2][1] = 2.f * C[2][3];                   T[2][2] = C[3][3];
        const float G[3][3] = {{0.5f, 0.5f, 0.f}, {0.f, 0.f, 0.5f}, {0.5f, -0.5f, 0.f}};
        #pragma unroll
        for (int rr = 0; rr < 3; ++rr)
            #pragma unroll
            for (int ss = 0; ss < 3; ++ss) {
                float k = 0.f;
                #pragma unroll
                for (int a = 0; a < 3; ++a)
                    #pragma unroll
                    for (int b2 = 0; b2 < 3; ++b2)
                        k += G[a][rr] * T[a][b2] * G[b2][ss];
                g_params.K[rr * 3 + ss] = k;
            }
        g_params.W0 = W[0];  g_params.W1 = W[1];
        g_params.b0 = bb[0]; g_params.b1 = bb[1];
    }
}

// ---------------- packed f32x2 helpers: FFMA2 ONLY (guaranteed packed) -------
__device__ __forceinline__ unsigned long long pk2(float lo, float hi) {
    unsigned long long d;
    asm("mov.b64 %0, {%1, %2};" : "=l"(d) : "r"(__float_as_uint(lo)), "r"(__float_as_uint(hi)));
    return d;
}
__device__ __forceinline__ void upk2(unsigned long long v, float& lo, float& hi) {
    unsigned int a, b;
    asm("mov.b64 {%0, %1}, %2;" : "=r"(a), "=r"(b) : "l"(v));
    lo = __uint_as_float(a); hi = __uint_as_float(b);
}
__device__ __forceinline__ unsigned long long fma2(unsigned long long a, unsigned long long b,
                                                   unsigned long long c) {
    unsigned long long d;
    asm("fma.rn.f32x2 %0, %1, %2, %3;" : "=l"(d) : "l"(a), "l"(b), "l"(c));
    return d;
}
// 8-byte shared load (uniform broadcast) as one ull
__device__ __forceinline__ unsigned long long lds64(const unsigned long long* p) {
    unsigned long long d;
    asm("ld.shared.b64 %0, [%1];" : "=l"(d) : "l"(__cvta_generic_to_shared(p)));
    return d;
}

// ---------------- main kernel: 4 batch elements per thread (2 f32x2 groups) --
__global__ __launch_bounds__(256) void qfcn_main(const float* __restrict__ x,
                                                 float2* __restrict__ out, int quart) {
    __shared__ Params sp;
    {
        const unsigned int* src = (const unsigned int*)&g_params;
        unsigned int* dst = (unsigned int*)&sp;
        for (int i = threadIdx.x; i < (int)(sizeof(Params) / 4); i += 256) dst[i] = src[i];
    }
    __syncthreads();

    int gid = blockIdx.x * 256 + threadIdx.x;
    if (gid >= quart) return;

    const float4* p0 = (const float4*)x + (size_t)gid * 4;
    const float4* p1 = (const float4*)x + ((size_t)gid + (size_t)quart) * 4;
    const float4* p2 = (const float4*)x + ((size_t)gid + 2 * (size_t)quart) * 4;
    const float4* p3 = (const float4*)x + ((size_t)gid + 3 * (size_t)quart) * 4;

    unsigned long long pa[16], pb[16];   // group A = elems {0,1}, group B = {2,3}
    #pragma unroll
    for (int q = 0; q < 4; ++q) {
        float4 u = __ldg(p0 + q), v = __ldg(p1 + q);
        pa[q * 4 + 0] = pk2(u.x, v.x); pa[q * 4 + 1] = pk2(u.y, v.y);
        pa[q * 4 + 2] = pk2(u.z, v.z); pa[q * 4 + 3] = pk2(u.w, v.w);
    }
    #pragma unroll
    for (int q = 0; q < 4; ++q) {
        float4 u = __ldg(p2 + q), v = __ldg(p3 + q);
        pb[q * 4 + 0] = pk2(u.x, v.x); pb[q * 4 + 1] = pk2(u.y, v.y);
        pb[q * 4 + 2] = pk2(u.z, v.z); pb[q * 4 + 3] = pk2(u.w, v.w);
    }

    const unsigned long long Z = 0ull;
    const unsigned long long ONE2 = pk2(1.0f, 1.0f);
    unsigned long long e1A = Z, e3A = Z, ssA = Z;
    unsigned long long e1B = Z, e3B = Z, ssB = Z;

    const unsigned long long* cp = (const unsigned long long*)sp.pair;  // [aa, bb] per pair
    int idx = 0;
    #pragma unroll
    for (int i = 0; i < 16; ++i) {
        #pragma unroll
        for (int j = i; j < 16; ++j) {
            unsigned long long prA = fma2(pa[i], pa[j], Z);
            unsigned long long prB = fma2(pb[i], pb[j], Z);
            unsigned long long ca = lds64(cp + 2 * idx);       // (a,a)
            unsigned long long cb = lds64(cp + 2 * idx + 1);   // (b,b)
            e1A = fma2(prA, ca, e1A);
            e1B = fma2(prB, ca, e1B);
            e3A = fma2(prA, cb, e3A);
            e3B = fma2(prB, cb, e3B);
            if (j == i) { ssA = fma2(prA, ONE2, ssA); ssB = fma2(prB, ONE2, ssB); }
            ++idx;
        }
    }

    const float K0 = sp.K[0], K1 = sp.K[1], K2 = sp.K[2];
    const float K3 = sp.K[3], K4 = sp.K[4], K5 = sp.K[5];
    const float K6 = sp.K[6], K7 = sp.K[7], K8 = sp.K[8];
    const float W0 = sp.W0, W1 = sp.W1, b0 = sp.b0, b1 = sp.b1;

    auto head = [&](float q1, float q3, float s) -> float2 {
        float inv = __fdividef(1.0f, s);
        float t1 = q1 * inv, t3 = q3 * inv;          // <Z_1>, <Z_3>  in [-1,1]
        float s1, c1, s2, c2;
        __sincosf(t1, &s1, &c1);
        __sincosf(t3, &s2, &c2);
        float e = K0 + K1 * c2 + K2 * s2
                + c1 * (K3 + K4 * c2 + K5 * s2)
                + s1 * (K6 + K7 * c2 + K8 * s2);
        return make_float2(fmaf(e, W0, b0), fmaf(e, W1, b1));
    };

    float e1a, e1b, e3a, e3b, sa, sb;
    upk2(e1A, e1a, e1b); upk2(e3A, e3a, e3b); upk2(ssA, sa, sb);
    out[gid]             = head(e1a, e3a, sa);
    out[gid + quart]     = head(e1b, e3b, sb);
    upk2(e1B, e1a, e1b); upk2(e3B, e3a, e3b); upk2(ssB, sa, sb);
    out[gid + 2 * quart] = head(e1a, e3a, sa);
    out[gid + 3 * quart] = head(e1b, e3b, sb);
}

extern "C" void kernel_launch(void* const* d_in, const int* in_sizes, int n_in,
                              void* d_out, int out_size) {
    const float* x  = (const float*)d_in[0];
    const float* f1 = (const float*)d_in[1];
    const float* p1 = (const float*)d_in[2];
    const float* f2 = (const float*)d_in[3];
    const float* p2 = (const float*)d_in[4];
    const float* W  = (const float*)d_in[5];
    const float* b  = (const float*)d_in[6];

    int B = in_sizes[0] / 16;
    int quart = B >> 2;

    setup_kernel<<<1, 256>>>(f1, p1, f2, p2, W, b);
    int blocks = (quart + 255) / 256;
    qfcn_main<<<blocks, 256>>>(x, (float2*)d_out, quart);
}

// round 4
// speedup vs baseline: 1.2092x; 1.2092x over previous
#include <cuda_runtime.h>

#define PI_F 3.14159265358979323846f

// ---------------- constant tables computed on-device from the small inputs ----
struct Params {
    float2 pair[136];   // (i<=j) upper-tri order: {a, b}, off-diag pre-doubled
    float  K[9];        // e = sum K[3r+s] * (1,C1,S1)_r * (1,C2,S2)_s
    float  W0, W1, b0, b1;
};
__device__ Params g_params;

// compile-time 16th-root twiddle table: W16[k] = (cos, sin)(2*pi*k/16)
__constant__ float2 W16[16] = {
    { 1.0000000000f,  0.0000000000f}, { 0.9238795325f,  0.3826834324f},
    { 0.7071067812f,  0.7071067812f}, { 0.3826834324f,  0.9238795325f},
    { 0.0000000000f,  1.0000000000f}, {-0.3826834324f,  0.9238795325f},
    {-0.7071067812f,  0.7071067812f}, {-0.9238795325f,  0.3826834324f},
    {-1.0000000000f,  0.0000000000f}, {-0.9238795325f, -0.3826834324f},
    {-0.7071067812f, -0.7071067812f}, {-0.3826834324f, -0.9238795325f},
    { 0.0000000000f, -1.0000000000f}, { 0.3826834324f, -0.9238795325f},
    { 0.7071067812f, -0.7071067812f}, { 0.9238795325f, -0.3826834324f}};

__device__ __forceinline__ float2 cmulf(float2 a, float2 b) {
    return make_float2(a.x * b.x - a.y * b.y, a.x * b.y + a.y * b.x);
}

// ---------------- setup: build U1 (16x16), U2 (4x4), fold into A/B/K ---------
__global__ void setup_kernel(const float* __restrict__ f1, const float* __restrict__ p1,
                             const float* __restrict__ f2, const float* __restrict__ p2,
                             const float* __restrict__ W, const float* __restrict__ bb) {
    __shared__ float2 U[256];
    __shared__ float2 V[256];
    __shared__ float2 U2s[16];
    __shared__ float2 V2s[16];

    const int t = threadIdx.x;
    const int r = t >> 4, c = t & 15;
    const float p1_0 = p1[0], p1_1 = p1[1];
    float sn_p11, cs_p11; sincosf(0.5f * p1_1, &sn_p11, &cs_p11);

    // ---- U1: init = (fused RZ diag) * QFT ----
    {
        float ph = 0.0f;
        ph += (((r >> 3) & 1) ? 0.5f : -0.5f) * f1[0];
        ph += (((r >> 2) & 1) ? 0.5f : -0.5f) * f1[1];
        ph += (((r >> 1) & 1) ? 0.5f : -0.5f) * f1[2];
        ph += (((r     ) & 1) ? 0.5f : -0.5f) * f1[3];
        float sp, cp; sincosf(ph, &sp, &cp);
        float2 w = W16[(r * c) & 15];
        U[t] = make_float2(0.25f * (w.x * cp - w.y * sp),
                           0.25f * (w.y * cp + w.x * sp));
    }
    __syncthreads();
    // Qdag @ U  (the only dense matmul) — twiddle conj from the constant table
    {
        float2 acc = make_float2(0.f, 0.f);
        #pragma unroll
        for (int k = 0; k < 16; ++k) {
            float2 w = W16[(r * k) & 15];      // conj(w) = (w.x, -w.y)
            float2 u = U[k * 16 + c];
            acc.x += w.x * u.x + w.y * u.y;
            acc.y += w.x * u.y - w.y * u.x;
        }
        V[t] = make_float2(0.25f * acc.x, 0.25f * acc.y);
    }
    __syncthreads();
    U[t] = V[t];
    __syncthreads();

    // g1: CRZ(p1_0) ctrl bit3, tgt bit2 (diag in-place)
    if ((r >> 3) & 1) {
        float ang = (((r >> 2) & 1) ? 0.5f : -0.5f) * p1_0;
        float sn, cs; sincosf(ang, &sn, &cs);
        U[t] = cmulf(U[t], make_float2(cs, sn));
    }
    __syncthreads();
    // g2: X mask 8
    V[t] = U[((r ^ 8) << 4) | c]; __syncthreads(); U[t] = V[t]; __syncthreads();
    // g3: CRX(p1_1) ctrl bit3, tgt mask 4
    {
        float2 u = U[t];
        if ((r >> 3) & 1) {
            float2 v = U[((r ^ 4) << 4) | c];
            u = make_float2(cs_p11 * u.x + sn_p11 * v.y, cs_p11 * u.y - sn_p11 * v.x);
        }
        V[t] = u;
    }
    __syncthreads(); U[t] = V[t]; __syncthreads();
    // g4: X mask 8
    V[t] = U[((r ^ 8) << 4) | c]; __syncthreads(); U[t] = V[t]; __syncthreads();
    // g5: CRZ(p1_0) ctrl bit1, tgt bit0
    if ((r >> 1) & 1) {
        float ang = ((r & 1) ? 0.5f : -0.5f) * p1_0;
        float sn, cs; sincosf(ang, &sn, &cs);
        U[t] = cmulf(U[t], make_float2(cs, sn));
    }
    __syncthreads();
    // g6: X mask 2
    V[t] = U[((r ^ 2) << 4) | c]; __syncthreads(); U[t] = V[t]; __syncthreads();
    // g7: CRX(p1_1) ctrl bit1, tgt mask 1
    {
        float2 u = U[t];
        if ((r >> 1) & 1) {
            float2 v = U[((r ^ 1) << 4) | c];
            u = make_float2(cs_p11 * u.x + sn_p11 * v.y, cs_p11 * u.y - sn_p11 * v.x);
        }
        V[t] = u;
    }
    __syncthreads(); U[t] = V[t]; __syncthreads();
    // g8: X mask 2
    V[t] = U[((r ^ 2) << 4) | c]; __syncthreads(); U[t] = V[t]; __syncthreads();

    // ---- pair table: A = Re(U1^H Z1 U1), B = Re(U1^H Z3 U1) ----
    if (r <= c) {
        const int i = r, j = c;
        float av = 0.f, bv = 0.f;
        #pragma unroll
        for (int m = 0; m < 16; ++m) {
            float2 ui = U[m * 16 + i], uj = U[m * 16 + j];
            float re = ui.x * uj.x + ui.y * uj.y;     // Re(conj(ui)*uj)
            float z1 = 1.f - 2.f * (float)((m >> 2) & 1);
            float z3 = 1.f - 2.f * (float)(m & 1);
            av += z1 * re;
            bv += z3 * re;
        }
        float w = (i < j) ? 2.f : 1.f;
        int idx = i * 16 - (i * (i - 1)) / 2 + (j - i);
        g_params.pair[idx] = make_float2(w * av, w * bv);
    }

    // ---- U2 (4x4) ----
    if (t < 16) {
        int r2 = t >> 2, c2 = t & 3;
        float ph = ((((r2 >> 1) & 1) ? 0.5f : -0.5f) * f2[0])
                 + ((( r2       & 1) ? 0.5f : -0.5f) * f2[1]);
        float sp, cp; sincosf(ph, &sp, &cp);
        float2 w = W16[((r2 * c2) & 3) * 4];
        U2s[t] = make_float2(0.5f * (w.x * cp - w.y * sp),
                             0.5f * (w.y * cp + w.x * sp));
    }
    __syncthreads();
    if (t < 16) {  // Q2dag @ U2
        int r2 = t >> 2, c2 = t & 3;
        float2 acc = make_float2(0.f, 0.f);
        #pragma unroll
        for (int k = 0; k < 4; ++k) {
            float2 w = W16[((r2 * k) & 3) * 4];   // use conj(w)
            float2 u = U2s[k * 4 + c2];
            acc.x += w.x * u.x + w.y * u.y;
            acc.y += w.x * u.y - w.y * u.x;
        }
        V2s[t] = make_float2(0.5f * acc.x, 0.5f * acc.y);
    }
    __syncthreads();
    if (t < 16) {  // CRZ(p2[0]) ctrl bit1, tgt bit0
        int r2 = t >> 2;
        float2 u = V2s[t];
        if ((r2 >> 1) & 1) {
            float ang = ((r2 & 1) ? 0.5f : -0.5f) * p2[0];
            float sn, cs; sincosf(ang, &sn, &cs);
            u = cmulf(u, make_float2(cs, sn));
        }
        U2s[t] = u;
    }
    __syncthreads();
    if (t < 16) {  // X mask 2
        int r2 = t >> 2, c2 = t & 3;
        V2s[t] = U2s[((r2 ^ 2) << 2) | c2];
    }
    __syncthreads();
    if (t < 16) {  // CRX(p2[1]) ctrl bit1, tgt mask 1
        int r2 = t >> 2, c2 = t & 3;
        float2 u = V2s[t];
        if ((r2 >> 1) & 1) {
            float sn, cs; sincosf(0.5f * p2[1], &sn, &cs);
            float2 v = V2s[((r2 ^ 1) << 2) | c2];
            u = make_float2(cs * u.x + sn * v.y, cs * u.y - sn * v.x);
        }
        U2s[t] = u;
    }
    __syncthreads();
    if (t < 16) {  // X mask 2 (final U2 ends in V2s)
        int r2 = t >> 2, c2 = t & 3;
        V2s[t] = U2s[((r2 ^ 2) << 2) | c2];
    }
    __syncthreads();

    // ---- fold layer-2 into K ----
    if (t == 0) {
        float C[4][4];
        #pragma unroll
        for (int i = 0; i < 4; ++i)
            #pragma unroll
            for (int j = 0; j < 4; ++j) {
                float acc = 0.f;
                #pragma unroll
                for (int m = 0; m < 4; ++m) {
                    float2 ui = V2s[m * 4 + i], uj = V2s[m * 4 + j];
                    float z = 1.f - 2.f * (float)(m & 1);
                    acc += z * (ui.x * uj.x + ui.y * uj.y);
                }
                C[i][j] = acc;
            }
        float T[3][3];
        T[0][0] = C[0][0];            T[0][1] = 2.f * C[0][1];                   T[0][2] = C[1][1];
        T[1][0] = 2.f * C[0][2];      T[1][1] = 2.f * C[0][3] + 2.f * C[1][2];   T[1][2] = 2.f * C[1][3];
        T[2][0] = C[2][2];            T[2][1] = 2.f * C[2][3];                   T[2][2] = C[3][3];
        const float G[3][3] = {{0.5f, 0.5f, 0.f}, {0.f, 0.f, 0.5f}, {0.5f, -0.5f, 0.f}};
        #pragma unroll
        for (int rr = 0; rr < 3; ++rr)
            #pragma unroll
            for (int ss = 0; ss < 3; ++ss) {
                float k = 0.f;
                #pragma unroll
                for (int a = 0; a < 3; ++a)
                    #pragma unroll
                    for (int b2 = 0; b2 < 3; ++b2)
                        k += G[a][rr] * T[a][b2] * G[b2][ss];
                g_params.K[rr * 3 + ss] = k;
            }
        g_params.W0 = W[0];  g_params.W1 = W[1];
        g_params.b0 = bb[0]; g_params.b1 = bb[1];
    }
}

// ---------------- main kernel: 2 batch elements per thread, pure scalar FFMA -
__global__ __launch_bounds__(256) void qfcn_main(const float* __restrict__ x,
                                                 float2* __restrict__ out, int half) {
    __shared__ float2 cpair[136];
    __shared__ float  cK[13];
    {
        int t = threadIdx.x;
        if (t < 136) cpair[t] = g_params.pair[t];
        if (t >= 136 && t < 149) cK[t - 136] = (&g_params.K[0])[t - 136];
    }
    __syncthreads();

    int gid = blockIdx.x * 256 + threadIdx.x;
    if (gid >= half) return;

    const float4* pa = (const float4*)x + (size_t)gid * 4;
    const float4* pb = (const float4*)x + ((size_t)gid + (size_t)half) * 4;

    float xa[16], xb[16];
    #pragma unroll
    for (int q = 0; q < 4; ++q) {
        float4 u = __ldg(pa + q);
        xa[q * 4 + 0] = u.x; xa[q * 4 + 1] = u.y; xa[q * 4 + 2] = u.z; xa[q * 4 + 3] = u.w;
        float4 v = __ldg(pb + q);
        xb[q * 4 + 0] = v.x; xb[q * 4 + 1] = v.y; xb[q * 4 + 2] = v.z; xb[q * 4 + 3] = v.w;
    }

    // 2-way split accumulators per output for ILP (10 independent FMA chains)
    float e1a0 = 0.f, e1a1 = 0.f, e3a0 = 0.f, e3a1 = 0.f, ssa = 0.f;
    float e1b0 = 0.f, e1b1 = 0.f, e3b0 = 0.f, e3b1 = 0.f, ssb = 0.f;

    int idx = 0;
    #pragma unroll
    for (int i = 0; i < 16; ++i) {
        #pragma unroll
        for (int j = i; j < 16; ++j) {
            float2 cc = cpair[idx];
            float ta = xa[i] * xa[j];
            float tb = xb[i] * xb[j];
            if (idx & 1) {
                e1a0 = fmaf(ta, cc.x, e1a0);  e3a0 = fmaf(ta, cc.y, e3a0);
                e1b0 = fmaf(tb, cc.x, e1b0);  e3b0 = fmaf(tb, cc.y, e3b0);
            } else {
                e1a1 = fmaf(ta, cc.x, e1a1);  e3a1 = fmaf(ta, cc.y, e3a1);
                e1b1 = fmaf(tb, cc.x, e1b1);  e3b1 = fmaf(tb, cc.y, e3b1);
            }
            if (j == i) { ssa += ta; ssb += tb; }
            ++idx;
        }
    }
    float e1a = e1a0 + e1a1, e3a = e3a0 + e3a1;
    float e1b = e1b0 + e1b1, e3b = e3b0 + e3b1;

    const float K0 = cK[0], K1 = cK[1], K2 = cK[2];
    const float K3 = cK[3], K4 = cK[4], K5 = cK[5];
    const float K6 = cK[6], K7 = cK[7], K8 = cK[8];
    const float W0 = cK[9], W1 = cK[10], b0 = cK[11], b1 = cK[12];

    auto head = [&](float q1, float q3, float s) -> float2 {
        float inv = __fdividef(1.0f, s);
        float t1 = q1 * inv, t3 = q3 * inv;          // <Z_1>, <Z_3>  in [-1,1]
        float s1, c1, s2, c2;
        __sincosf(t1, &s1, &c1);
        __sincosf(t3, &s2, &c2);
        float e = K0 + K1 * c2 + K2 * s2
                + c1 * (K3 + K4 * c2 + K5 * s2)
                + s1 * (K6 + K7 * c2 + K8 * s2);
        return make_float2(fmaf(e, W0, b0), fmaf(e, W1, b1));
    };

    out[gid]        = head(e1a, e3a, ssa);
    out[gid + half] = head(e1b, e3b, ssb);
}

extern "C" void kernel_launch(void* const* d_in, const int* in_sizes, int n_in,
                              void* d_out, int out_size) {
    const float* x  = (const float*)d_in[0];
    const float* f1 = (const float*)d_in[1];
    const float* p1 = (const float*)d_in[2];
    const float* f2 = (const float*)d_in[3];
    const float* p2 = (const float*)d_in[4];
    const float* W  = (const float*)d_in[5];
    const float* b  = (const float*)d_in[6];

    int B = in_sizes[0] / 16;
    int half = B >> 1;

    setup_kernel<<<1, 256>>>(f1, p1, f2, p2, W, b);
    int blocks = (half + 255) / 256;
    qfcn_main<<<blocks, 256>>>(x, (float2*)d_out, half);
}